// round 3
// baseline (speedup 1.0000x reference)
#include <cuda_runtime.h>
#include <cstdint>

// FP4Quantizer, 2-node pipeline:
//   pass1: stage 32KB/CTA -> smem; thread-per-64-block top-5 selection
//          (branchless u32 insertion network); quantize to 4-bit codes
//          (sign|level) packed 8/word; per-block scale; fence-counter
//          last-CTA reduction of global scale min/max (no init kernel).
//   pass2: decode codes -> out. Reads 9MB (L2-hot), writes 64MB.

#define QBLK 64
#define CTA_BLOCKS 128
#define P1_THREADS 128
#define MAX_QBLOCKS (262144 + 8192)
#define MAX_GRID1   ((MAX_QBLOCKS + CTA_BLOCKS - 1) / CTA_BLOCKS + 8)

__device__ float    g_scales[MAX_QBLOCKS];
__device__ unsigned g_codes[MAX_QBLOCKS * 8];   // 8 x u32 per block (4-bit codes)
__device__ unsigned g_pmin[MAX_GRID1];
__device__ unsigned g_pmax[MAX_GRID1];
__device__ unsigned g_ctr = 0;                  // wraps to 0 every launch
__device__ float4   g_gmm;                      // (smin, ss, rss, -)

__device__ __forceinline__ unsigned absbits(float f) {
    return __float_as_uint(f) & 0x7FFFFFFFu;
}

// top-5 insertion (descending m0..m4), branchless u32 min/max
#define INS5(v) do { \
    unsigned _v = (v); \
    unsigned h0 = max(m0, _v), l0 = min(m0, _v); \
    unsigned h1 = max(m1, l0), l1 = min(m1, l0); \
    unsigned h2 = max(m2, l1), l2 = min(m2, l1); \
    unsigned h3 = max(m3, l2), l3 = min(m3, l2); \
    unsigned h4 = max(m4, l3); \
    m0 = h0; m1 = h1; m2 = h2; m3 = h3; m4 = h4; \
} while (0)

// quantize one value -> 4-bit code (bit3 = sign, bits0-2 = level index 0..5)
// level set {0, 0.75, 1, 1.5, 2, 3}: round |x/s| to 1 mantissa bit, clamp
// [0.75, 3.0] in u32 domain, zero at/below 0.375 (argmin tie-to-lower).
__device__ __forceinline__ unsigned qnib(float xv, float inv) {
    float xs = xv * inv;
    unsigned ub = __float_as_uint(xs);
    unsigned uu = ub & 0x7FFFFFFFu;
    unsigned t  = (uu + 0x00200000u) & 0xFFC00000u;
    t = t < 0x40400000u ? t : 0x40400000u;
    t = t > 0x3F400000u ? t : 0x3F400000u;
    unsigned idx = (uu > 0x3EC00000u) ? ((t >> 22) - 0xFCu) : 0u;  // 0..5
    return idx | ((ub >> 28) & 8u);                                // sign->bit3
}

__global__ void __launch_bounds__(P1_THREADS)
pass1_kernel(const float* __restrict__ x, int n, int nblocks) {
    __shared__ float    sdata[4 * 32 * 68];       // 68-float rows: LDS/STS conflict-free
    __shared__ unsigned s_rmin[4], s_rmax[4];
    __shared__ int      s_last;

    const int tid  = threadIdx.x;
    const int w    = tid >> 5;
    const int lane = tid & 31;
    const long cta_block0 = (long)blockIdx.x * CTA_BLOCKS;

    // ---- stage: warp w loads blocks [cta_block0 + 32w, +32) = 8KB contiguous
    {
        long ebase = (cta_block0 + (w << 5)) * QBLK;
        const float4* __restrict__ x4 = reinterpret_cast<const float4*>(x);
        #pragma unroll
        for (int k = 0; k < 16; ++k) {
            int  f = (k << 5) + lane;              // float4 idx within 2048-float chunk
            long e = ebase + (long)(f << 2);
            float4 v;
            if (e + 3 < (long)n) {
                v = x4[(ebase >> 2) + f];
            } else {
                v = make_float4(0.f, 0.f, 0.f, 0.f);
                if (e     < (long)n) v.x = x[e];
                if (e + 1 < (long)n) v.y = x[e + 1];
                if (e + 2 < (long)n) v.z = x[e + 2];
            }
            int row = f >> 4, colq = f & 15;
            *reinterpret_cast<float4*>(&sdata[((w << 5) + row) * 68 + (colq << 2)]) = v;
        }
    }
    __syncwarp();   // each warp consumes only its own staged region

    // ---- thread tid owns block cta_block0 + tid (row tid&31 of warp tid>>5)
    unsigned mymin = 0xFFFFFFFFu, mymax = 0u;
    long myblock = cta_block0 + tid;
    if (myblock < (long)nblocks) {
        const float4* __restrict__ srow =
            reinterpret_cast<const float4*>(&sdata[tid * 68]);

        unsigned m0 = 0u, m1 = 0u, m2 = 0u, m3 = 0u, m4 = 0u;
        #pragma unroll
        for (int jj = 0; jj < 16; ++jj) {
            float4 v = srow[jj];
            INS5(absbits(v.x)); INS5(absbits(v.y));
            INS5(absbits(v.z)); INS5(absbits(v.w));
        }
        float q4 = __uint_as_float(m3);            // 4th largest (sorted[60])
        float q5 = __uint_as_float(m4);            // 5th largest (sorted[59])
        float s  = fmaxf(fmaf(0.85f, q4 - q5, q5), 1e-8f);
        g_scales[myblock] = s;
        unsigned sb = __float_as_uint(s);
        mymin = sb; mymax = sb;

        // ---- quantize + pack (8 nibbles per u32)
        float inv = 1.0f / s;
        unsigned cw[8];
        #pragma unroll
        for (int wq = 0; wq < 8; ++wq) {
            float4 a = srow[wq * 2];
            float4 b = srow[wq * 2 + 1];
            unsigned c = qnib(a.x, inv);
            c |= qnib(a.y, inv) << 4;
            c |= qnib(a.z, inv) << 8;
            c |= qnib(a.w, inv) << 12;
            c |= qnib(b.x, inv) << 16;
            c |= qnib(b.y, inv) << 20;
            c |= qnib(b.z, inv) << 24;
            c |= qnib(b.w, inv) << 28;
            cw[wq] = c;
        }
        uint4* cp = reinterpret_cast<uint4*>(&g_codes[myblock * 8]);
        cp[0] = make_uint4(cw[0], cw[1], cw[2], cw[3]);
        cp[1] = make_uint4(cw[4], cw[5], cw[6], cw[7]);
    }

    // ---- CTA reduce of scale min/max -> per-CTA partials
    mymin = __reduce_min_sync(0xFFFFFFFFu, mymin);
    mymax = __reduce_max_sync(0xFFFFFFFFu, mymax);
    if (lane == 0) { s_rmin[w] = mymin; s_rmax[w] = mymax; }
    __syncthreads();
    if (tid == 0) {
        unsigned a = 0xFFFFFFFFu, b = 0u;
        #pragma unroll
        for (int i = 0; i < 4; ++i) {
            a = a < s_rmin[i] ? a : s_rmin[i];
            b = b > s_rmax[i] ? b : s_rmax[i];
        }
        g_pmin[blockIdx.x] = a;
        g_pmax[blockIdx.x] = b;
        __threadfence();
        unsigned old = atomicInc(&g_ctr, gridDim.x - 1);   // wraps to 0 each launch
        s_last = (old == gridDim.x - 1);
    }
    __syncthreads();

    // ---- last CTA: reduce partials, publish (smin, ss, rss)
    if (s_last) {
        unsigned lmin = 0xFFFFFFFFu, lmax = 0u;
        for (int i = tid; i < (int)gridDim.x; i += P1_THREADS) {
            unsigned a = __ldcg(&g_pmin[i]);
            unsigned b = __ldcg(&g_pmax[i]);
            lmin = lmin < a ? lmin : a;
            lmax = lmax > b ? lmax : b;
        }
        lmin = __reduce_min_sync(0xFFFFFFFFu, lmin);
        lmax = __reduce_max_sync(0xFFFFFFFFu, lmax);
        if (lane == 0) { s_rmin[w] = lmin; s_rmax[w] = lmax; }
        __syncthreads();
        if (tid == 0) {
            unsigned a = 0xFFFFFFFFu, b = 0u;
            #pragma unroll
            for (int i = 0; i < 4; ++i) {
                a = a < s_rmin[i] ? a : s_rmin[i];
                b = b > s_rmax[i] ? b : s_rmax[i];
            }
            float smin = __uint_as_float(a);
            float smax = __uint_as_float(b);
            bool  cond = smax > smin;
            float d    = smax - smin;
            float ss   = cond ? d * (1.0f / 255.0f) : 1.0f;
            float rss  = cond ? 255.0f / d : 0.0f;
            g_gmm = make_float4(smin, ss, rss, 0.0f);
        }
    }
}

// decode nibble -> level * deq with sign
__device__ __forceinline__ float dec(unsigned nib, float deq) {
    unsigned lvl  = nib & 7u;
    unsigned bits = lvl ? (0x3F000000u + (lvl << 22)) : 0u;
    float o = __uint_as_float(bits) * deq;
    return __uint_as_float(__float_as_uint(o) | ((nib & 8u) << 28));
}

__device__ __forceinline__ float deq_of(float s, float smin, float rss, float ss) {
    float q = rintf((s - smin) * rss);
    q = fminf(fmaxf(q, 0.0f), 255.0f);
    return q * ss;
}

__global__ void pass2_kernel(float* __restrict__ out, int n) {
    const int tid = blockIdx.x * blockDim.x + threadIdx.x;
    const int NT  = gridDim.x * blockDim.x;
    const int nquads = n >> 2;

    float4 gmm = g_gmm;
    const float smin = gmm.x, ss = gmm.y, rss = gmm.z;

    float4* __restrict__ o4 = reinterpret_cast<float4*>(out);

    for (int q = tid; q < nquads; q += NT) {
        unsigned cw   = g_codes[q >> 1];
        unsigned nib4 = (q & 1) ? (cw >> 16) : cw;       // 4 nibbles
        float sc  = g_scales[q >> 4];
        float deq = deq_of(sc, smin, rss, ss);
        float4 r;
        r.x = dec( nib4        & 0xFu, deq);
        r.y = dec((nib4 >> 4)  & 0xFu, deq);
        r.z = dec((nib4 >> 8)  & 0xFu, deq);
        r.w = dec((nib4 >> 12) & 0xFu, deq);
        __stcs(o4 + q, r);
    }
    for (int e = (nquads << 2) + tid; e < n; e += NT) {  // scalar tail
        unsigned cw  = g_codes[e >> 3];
        unsigned nib = (cw >> ((e & 7) << 2)) & 0xFu;
        float deq = deq_of(g_scales[e >> 6], smin, rss, ss);
        out[e] = dec(nib, deq);
    }
}

extern "C" void kernel_launch(void* const* d_in, const int* in_sizes, int n_in,
                              void* d_out, int out_size) {
    const float* x = (const float*)d_in[0];
    float* out = (float*)d_out;
    int n = in_sizes[0];
    int nblocks = (n + QBLK - 1) / QBLK;
    int grid1 = (nblocks + CTA_BLOCKS - 1) / CTA_BLOCKS;

    pass1_kernel<<<grid1, P1_THREADS>>>(x, n, nblocks);
    pass2_kernel<<<4096, 256>>>(out, n);
}

// round 5
// speedup vs baseline: 1.2209x; 1.2209x over previous
#include <cuda_runtime.h>
#include <cstdint>

// FP4Quantizer, 2-node pipeline:
//   pass1: per-64-block scale via 5-REDUX top-5 selection (clear-all-ties,
//          paired rank4/rank5 extraction), ILP-2 over block pairs;
//          fence-counter last-CTA reduction publishes (smin, ss, rss).
//   pass2: elementwise quantize-dequantize re-reading x (L2-hot), 4-way
//          batched loads + streaming stores.

#define QBLK 64
#define MAX_QBLOCKS (262144 + 8192)
#define MAX_GRID1   8192

__device__ float2   g_bs[MAX_QBLOCKS];   // (inv_scale, scale)
__device__ unsigned g_pmin[MAX_GRID1];
__device__ unsigned g_pmax[MAX_GRID1];
__device__ unsigned g_ctr = 0;           // wraps to 0 every launch
__device__ float4   g_gmm;               // (smin, ss, rss, -)

__device__ __forceinline__ unsigned absbits(float f) {
    return __float_as_uint(f) & 0x7FFFFFFFu;
}

// CTA partial -> global publish -> last CTA computes (smin, ss, rss).
__device__ __forceinline__ void reduce_and_publish(unsigned mymin, unsigned mymax,
                                                   int tid, int lane, int w) {
    __shared__ unsigned s_rmin[8], s_rmax[8];
    __shared__ int s_last;
    mymin = __reduce_min_sync(0xFFFFFFFFu, mymin);
    mymax = __reduce_max_sync(0xFFFFFFFFu, mymax);
    if (lane == 0) { s_rmin[w] = mymin; s_rmax[w] = mymax; }
    __syncthreads();
    if (tid == 0) {
        unsigned a = 0xFFFFFFFFu, b = 0u;
        int nwc = blockDim.x >> 5;
        for (int i = 0; i < nwc; ++i) {
            a = a < s_rmin[i] ? a : s_rmin[i];
            b = b > s_rmax[i] ? b : s_rmax[i];
        }
        g_pmin[blockIdx.x] = a;
        g_pmax[blockIdx.x] = b;
        __threadfence();
        unsigned old = atomicInc(&g_ctr, gridDim.x - 1);  // wraps to 0 each launch
        s_last = (old == gridDim.x - 1);
    }
    __syncthreads();
    if (s_last) {
        unsigned lmin = 0xFFFFFFFFu, lmax = 0u;
        for (int i = tid; i < (int)gridDim.x; i += blockDim.x) {
            unsigned a = __ldcg(&g_pmin[i]);
            unsigned b = __ldcg(&g_pmax[i]);
            lmin = lmin < a ? lmin : a;
            lmax = lmax > b ? lmax : b;
        }
        lmin = __reduce_min_sync(0xFFFFFFFFu, lmin);
        lmax = __reduce_max_sync(0xFFFFFFFFu, lmax);
        if (lane == 0) { s_rmin[w] = lmin; s_rmax[w] = lmax; }
        __syncthreads();
        if (tid == 0) {
            unsigned a = 0xFFFFFFFFu, b = 0u;
            int nwc = blockDim.x >> 5;
            for (int i = 0; i < nwc; ++i) {
                a = a < s_rmin[i] ? a : s_rmin[i];
                b = b > s_rmax[i] ? b : s_rmax[i];
            }
            float smin = __uint_as_float(a);
            float smax = __uint_as_float(b);
            bool  cond = smax > smin;
            float dd   = smax - smin;
            float ss   = cond ? dd * (1.0f / 255.0f) : 1.0f;
            float rss  = cond ? 255.0f / dd : 0.0f;
            g_gmm = make_float4(smin, ss, rss, 0.0f);
        }
    }
}

// ---------------- Pass 1 (fast path: n % 128 == 0) ----------------
// One warp processes TWO 64-elem blocks per iteration, interleaved for ILP.
// Positive-float bit patterns are order-preserving as u32, so REDUX.MAX on
// bits == max on |x|. Rounds 1-3 extract and clear the top-3 (clearing all
// bit-exact ties: probability ~1e-4/block, effect << rel tolerance). Round 4:
// w4 = max of remainder; w5 = max of remainder with w4-holders substituting
// their second value. quantile(0.95, 64) = s[59] + 0.85*(s[60]-s[59]).
__global__ void __launch_bounds__(256)
pass1_pair(const float* __restrict__ x, int npairs) {
    const int tid  = threadIdx.x;
    const int lane = tid & 31;
    const int w    = tid >> 5;
    const int warp = (blockIdx.x * blockDim.x + tid) >> 5;
    const int nw   = (gridDim.x * blockDim.x) >> 5;
    unsigned mymin = 0xFFFFFFFFu, mymax = 0u;

    for (int p = warp; p < npairs; p += nw) {
        long base = (long)p * (2 * QBLK) + lane * 2;
        float2 u = *reinterpret_cast<const float2*>(x + base);
        float2 v = *reinterpret_cast<const float2*>(x + base + QBLK);
        unsigned a0 = absbits(u.x), a1 = absbits(u.y);
        unsigned c0 = absbits(v.x), c1 = absbits(v.y);

        // rounds 1-3: extract + clear-all-ties
        #pragma unroll
        for (int r = 0; r < 3; ++r) {
            unsigned ma = max(a0, a1);
            unsigned mb = max(c0, c1);
            unsigned wa = __reduce_max_sync(0xFFFFFFFFu, ma);
            unsigned wb = __reduce_max_sync(0xFFFFFFFFu, mb);
            a0 = (a0 == wa) ? 0u : a0;
            a1 = (a1 == wa) ? 0u : a1;
            c0 = (c0 == wb) ? 0u : c0;
            c1 = (c1 == wb) ? 0u : c1;
        }
        // round 4+5 paired: w4 = max(rem); w5 = max(rem minus w4-instances,
        // with holders contributing their second value)
        unsigned ma = max(a0, a1);
        unsigned mb = max(c0, c1);
        unsigned w4a = __reduce_max_sync(0xFFFFFFFFu, ma);
        unsigned w4b = __reduce_max_sync(0xFFFFFFFFu, mb);
        unsigned ca = (ma == w4a) ? min(a0, a1) : ma;
        unsigned cb = (mb == w4b) ? min(c0, c1) : mb;
        unsigned w5a = __reduce_max_sync(0xFFFFFFFFu, ca);
        unsigned w5b = __reduce_max_sync(0xFFFFFFFFu, cb);

        if (lane == 0) {
            float q4a = __uint_as_float(w4a), q5a = __uint_as_float(w5a);
            float q4b = __uint_as_float(w4b), q5b = __uint_as_float(w5b);
            float sA = fmaxf(fmaf(0.85f, q4a - q5a, q5a), 1e-8f);
            float sB = fmaxf(fmaf(0.85f, q4b - q5b, q5b), 1e-8f);
            g_bs[2 * p]     = make_float2(1.0f / sA, sA);
            g_bs[2 * p + 1] = make_float2(1.0f / sB, sB);
            unsigned sa = __float_as_uint(sA), sb = __float_as_uint(sB);
            unsigned lo = sa < sb ? sa : sb;
            unsigned hi = sa > sb ? sa : sb;
            mymin = mymin < lo ? mymin : lo;
            mymax = mymax > hi ? mymax : hi;
        }
    }
    reduce_and_publish(mymin, mymax, tid, lane, w);
}

// ---------------- Pass 1 (generic fallback, any n) ----------------
__global__ void __launch_bounds__(256)
pass1_generic(const float* __restrict__ x, int n, int nblocks) {
    const int tid  = threadIdx.x;
    const int lane = tid & 31;
    const int w    = tid >> 5;
    const int warp = (blockIdx.x * blockDim.x + tid) >> 5;
    const int nw   = (gridDim.x * blockDim.x) >> 5;
    unsigned mymin = 0xFFFFFFFFu, mymax = 0u;

    for (int b = warp; b < nblocks; b += nw) {
        long base = (long)b * QBLK + lane * 2;
        float x0 = 0.0f, x1 = 0.0f;
        if (base + 1 < (long)n) {
            float2 t = *reinterpret_cast<const float2*>(x + base);
            x0 = t.x; x1 = t.y;
        } else if (base < (long)n) {
            x0 = x[base];
        }
        unsigned a0 = absbits(x0), a1 = absbits(x1);
        #pragma unroll
        for (int r = 0; r < 3; ++r) {
            unsigned m = max(a0, a1);
            unsigned ww = __reduce_max_sync(0xFFFFFFFFu, m);
            a0 = (a0 == ww) ? 0u : a0;
            a1 = (a1 == ww) ? 0u : a1;
        }
        unsigned m  = max(a0, a1);
        unsigned w4 = __reduce_max_sync(0xFFFFFFFFu, m);
        unsigned c  = (m == w4) ? min(a0, a1) : m;
        unsigned w5 = __reduce_max_sync(0xFFFFFFFFu, c);
        if (lane == 0) {
            float q4 = __uint_as_float(w4), q5 = __uint_as_float(w5);
            float s = fmaxf(fmaf(0.85f, q4 - q5, q5), 1e-8f);
            g_bs[b] = make_float2(1.0f / s, s);
            unsigned sb = __float_as_uint(s);
            mymin = mymin < sb ? mymin : sb;
            mymax = mymax > sb ? mymax : sb;
        }
    }
    reduce_and_publish(mymin, mymax, tid, lane, w);
}

// ---------------- Pass 2 ----------------
// Branchless nearest-level for {0, ±0.75, ±1, ±1.5, ±2, ±3}: round |x/s| to
// 1 mantissa bit, clamp [0.75, 3.0] as u32, zero at/below 0.375, multiply by
// deq, restore sign.
__device__ __forceinline__ float qdq_one(float xv, float inv, float deq) {
    float xs = xv * inv;
    unsigned ub = __float_as_uint(xs);
    unsigned uu = ub & 0x7FFFFFFFu;
    unsigned t  = (uu + 0x00200000u) & 0xFFC00000u;
    t = t < 0x40400000u ? t : 0x40400000u;
    t = t > 0x3F400000u ? t : 0x3F400000u;
    float lvl = (uu > 0x3EC00000u) ? __uint_as_float(t) : 0.0f;
    float o = lvl * deq;
    return __uint_as_float(__float_as_uint(o) | (ub & 0x80000000u));
}

__device__ __forceinline__ float deq_of(float s, float smin, float rss, float ss) {
    float q = rintf((s - smin) * rss);
    q = fminf(fmaxf(q, 0.0f), 255.0f);
    return q * ss;
}

__global__ void __launch_bounds__(256)
pass2_kernel(const float* __restrict__ x, float* __restrict__ out, int n) {
    const int tid = blockIdx.x * blockDim.x + threadIdx.x;
    const int NT  = gridDim.x * blockDim.x;
    const int nquads = n >> 2;

    float4 gmm = g_gmm;
    const float smin = gmm.x, ss = gmm.y, rss = gmm.z;

    const float4* __restrict__ x4 = reinterpret_cast<const float4*>(x);
    float4* __restrict__ o4 = reinterpret_cast<float4*>(out);

    int q = tid;
    for (; q + 3 * NT < nquads; q += 4 * NT) {
        int q1 = q + NT, q2 = q + 2 * NT, q3 = q + 3 * NT;
        float2 b0 = g_bs[q  >> 4];
        float2 b1 = g_bs[q1 >> 4];
        float2 b2 = g_bs[q2 >> 4];
        float2 b3 = g_bs[q3 >> 4];
        float4 v0 = x4[q],  v1 = x4[q1], v2 = x4[q2], v3 = x4[q3];
        float d0 = deq_of(b0.y, smin, rss, ss);
        float d1 = deq_of(b1.y, smin, rss, ss);
        float d2 = deq_of(b2.y, smin, rss, ss);
        float d3 = deq_of(b3.y, smin, rss, ss);
        float4 r0, r1, r2, r3;
        r0.x = qdq_one(v0.x, b0.x, d0); r0.y = qdq_one(v0.y, b0.x, d0);
        r0.z = qdq_one(v0.z, b0.x, d0); r0.w = qdq_one(v0.w, b0.x, d0);
        r1.x = qdq_one(v1.x, b1.x, d1); r1.y = qdq_one(v1.y, b1.x, d1);
        r1.z = qdq_one(v1.z, b1.x, d1); r1.w = qdq_one(v1.w, b1.x, d1);
        r2.x = qdq_one(v2.x, b2.x, d2); r2.y = qdq_one(v2.y, b2.x, d2);
        r2.z = qdq_one(v2.z, b2.x, d2); r2.w = qdq_one(v2.w, b2.x, d2);
        r3.x = qdq_one(v3.x, b3.x, d3); r3.y = qdq_one(v3.y, b3.x, d3);
        r3.z = qdq_one(v3.z, b3.x, d3); r3.w = qdq_one(v3.w, b3.x, d3);
        __stcs(o4 + q,  r0);
        __stcs(o4 + q1, r1);
        __stcs(o4 + q2, r2);
        __stcs(o4 + q3, r3);
    }
    for (; q < nquads; q += NT) {
        float2 b = g_bs[q >> 4];
        float dq = deq_of(b.y, smin, rss, ss);
        float4 v = x4[q];
        float4 r;
        r.x = qdq_one(v.x, b.x, dq); r.y = qdq_one(v.y, b.x, dq);
        r.z = qdq_one(v.z, b.x, dq); r.w = qdq_one(v.w, b.x, dq);
        __stcs(o4 + q, r);
    }
    for (int i = (nquads << 2) + tid; i < n; i += NT) {
        float2 b = g_bs[i >> 6];
        float dq = deq_of(b.y, smin, rss, ss);
        out[i] = qdq_one(x[i], b.x, dq);
    }
}

extern "C" void kernel_launch(void* const* d_in, const int* in_sizes, int n_in,
                              void* d_out, int out_size) {
    const float* x = (const float*)d_in[0];
    float* out = (float*)d_out;
    int n = in_sizes[0];
    int nblocks = (n + QBLK - 1) / QBLK;

    if ((n & 127) == 0) {
        int npairs = n >> 7;
        int grid = 4096;
        pass1_pair<<<grid, 256>>>(x, npairs);
    } else {
        pass1_generic<<<4096, 256>>>(x, n, nblocks);
    }
    pass2_kernel<<<4096, 256>>>(x, out, n);
}